// round 1
// baseline (speedup 1.0000x reference)
#include <cuda_runtime.h>

// Generator3DLUT_identity: trilinear 3D LUT apply.
//   in0: lut  float32 (3, 33, 33, 33)   = 107,811 elems
//   in1: x    float32 (8, 3, 1024, 1024) = 25,165,824 elems
//   out:      float32 (8, 3, 1024, 1024)
//
// Strategy:
//   kernel 1: zero the not-identity flag (graph replays must be deterministic)
//   kernel 2: repack lut -> float4 (RGB interleaved, 1 L2 sector per corner)
//             and check whether lut is the exact identity ramp (i/32)
//   kernel 3: if identity -> out = x * (1/1.000001)  (pure HBM stream)
//             else        -> full trilinear gather from packed LUT

#define DIM   33
#define DIM2  (DIM * DIM)       // 1089
#define DIM3  (DIM * DIM * DIM) // 35937

// Scratch: __device__ globals (no allocation allowed in kernel_launch).
__device__ float4 g_lut4[DIM3];
__device__ int    g_not_identity;

__global__ void init_flag_kernel() {
    g_not_identity = 0;
}

__global__ void pack_lut_kernel(const float* __restrict__ lut) {
    int i = blockIdx.x * blockDim.x + threadIdx.x;
    if (i >= DIM3) return;
    float r = lut[i];
    float g = lut[DIM3 + i];
    float b = lut[2 * DIM3 + i];
    g_lut4[i] = make_float4(r, g, b, 0.0f);

    // identity check: lut[0][b][g][r] = r/32, lut[1][..] = g/32, lut[2][..] = b/32
    int ri = i % DIM;
    int gi = (i / DIM) % DIM;
    int bi = i / DIM2;
    const float s = 1.0f / 32.0f;
    float er = (float)ri * s;
    float eg = (float)gi * s;
    float eb = (float)bi * s;
    if (fabsf(r - er) > 2e-6f || fabsf(g - eg) > 2e-6f || fabsf(b - eb) > 2e-6f) {
        atomicOr(&g_not_identity, 1);
    }
}

__device__ __forceinline__ float4 lerp4(float4 a, float4 b, float t) {
    float4 o;
    o.x = fmaf(t, b.x - a.x, a.x);
    o.y = fmaf(t, b.y - a.y, a.y);
    o.z = fmaf(t, b.z - a.z, a.z);
    o.w = 0.0f;
    return o;
}

__device__ __forceinline__ void trilinear_one(float r, float g, float b,
                                              float& orr, float& ogg, float& obb) {
    // binsize = 1.000001/32 ; rs = r / binsize = r * (32/1.000001)
    const float invbin = 32.0f / 1.000001f;
    float rs = r * invbin, gs = g * invbin, bs = b * invbin;
    float rf = floorf(rs), gf = floorf(gs), bf = floorf(bs);
    // deltas use the true floor (matches reference)
    float rd = rs - rf, gd = gs - gf, bd = bs - bf;
    int ri = (int)rf, gi = (int)gf, bi = (int)bf;
    // safety clamp so ri+1 <= 32 (inputs in [0,1) keep this a no-op)
    ri = min(max(ri, 0), DIM - 2);
    gi = min(max(gi, 0), DIM - 2);
    bi = min(max(bi, 0), DIM - 2);

    int base = (bi * DIM + gi) * DIM + ri;
    const float4* __restrict__ L = g_lut4;

    float4 c00 = lerp4(__ldg(&L[base]),              __ldg(&L[base + 1]),              rd);
    float4 c01 = lerp4(__ldg(&L[base + DIM]),        __ldg(&L[base + DIM + 1]),        rd);
    float4 c10 = lerp4(__ldg(&L[base + DIM2]),       __ldg(&L[base + DIM2 + 1]),       rd);
    float4 c11 = lerp4(__ldg(&L[base + DIM2 + DIM]), __ldg(&L[base + DIM2 + DIM + 1]), rd);

    float4 c0 = lerp4(c00, c01, gd);
    float4 c1 = lerp4(c10, c11, gd);
    float4 c  = lerp4(c0, c1, bd);
    orr = c.x; ogg = c.y; obb = c.z;
}

// x layout per image: [3][1024*1024] planes; 8 images.
// Each thread handles 4 consecutive pixels (float4) of one image.
#define PIX_PER_IMG   (1024 * 1024)          // 2^20
#define VEC_PER_IMG   (PIX_PER_IMG / 4)      // 2^18
#define TOTAL_VEC     (8 * VEC_PER_IMG)      // 2^21
#define THREADS       256

__global__ __launch_bounds__(THREADS)
void apply_lut_kernel(const float* __restrict__ x, float* __restrict__ out) {
    int idx = blockIdx.x * THREADS + threadIdx.x;   // < 2^21, exact grid
    int img = idx >> 18;
    int off = (idx & (VEC_PER_IMG - 1)) << 2;       // float offset within plane

    long long ibase = (long long)img * (3LL * PIX_PER_IMG) + off;
    const float4 r4 = *(const float4*)(x + ibase);
    const float4 g4 = *(const float4*)(x + ibase + PIX_PER_IMG);
    const float4 b4 = *(const float4*)(x + ibase + 2 * PIX_PER_IMG);

    float4 orr, ogg, obb;

    if (g_not_identity == 0) {
        // Identity LUT: trilinear interp of a linear ramp == x / 1.000001
        const float s = 1.0f / 1.000001f;
        orr.x = r4.x * s; orr.y = r4.y * s; orr.z = r4.z * s; orr.w = r4.w * s;
        ogg.x = g4.x * s; ogg.y = g4.y * s; ogg.z = g4.z * s; ogg.w = g4.w * s;
        obb.x = b4.x * s; obb.y = b4.y * s; obb.z = b4.z * s; obb.w = b4.w * s;
    } else {
        trilinear_one(r4.x, g4.x, b4.x, orr.x, ogg.x, obb.x);
        trilinear_one(r4.y, g4.y, b4.y, orr.y, ogg.y, obb.y);
        trilinear_one(r4.z, g4.z, b4.z, orr.z, ogg.z, obb.z);
        trilinear_one(r4.w, g4.w, b4.w, orr.w, ogg.w, obb.w);
    }

    *(float4*)(out + ibase)                    = orr;
    *(float4*)(out + ibase + PIX_PER_IMG)      = ogg;
    *(float4*)(out + ibase + 2 * PIX_PER_IMG)  = obb;
}

extern "C" void kernel_launch(void* const* d_in, const int* in_sizes, int n_in,
                              void* d_out, int out_size) {
    const float* lut = (const float*)d_in[0];
    const float* x   = (const float*)d_in[1];
    // defensive: identify lut by element count (3*33^3 = 107811)
    if (n_in >= 2 && in_sizes[0] != 3 * DIM3 && in_sizes[1] == 3 * DIM3) {
        lut = (const float*)d_in[1];
        x   = (const float*)d_in[0];
    }
    float* out = (float*)d_out;

    init_flag_kernel<<<1, 1>>>();
    pack_lut_kernel<<<(DIM3 + 255) / 256, 256>>>(lut);
    apply_lut_kernel<<<TOTAL_VEC / THREADS, THREADS>>>(x, out);
}

// round 2
// speedup vs baseline: 1.0510x; 1.0510x over previous
#include <cuda_runtime.h>

// Generator3DLUT_identity: trilinear 3D LUT apply.
//   in0: lut  float32 (3, 33, 33, 33)   = 107,811 elems
//   in1: x    float32 (8, 3, 1024, 1024) = 25,165,824 elems
//   out:      float32 (8, 3, 1024, 1024)
//
// Structure (2 launches):
//   kernel 1: check whether lut == identity ramp (lut[c][b][g][r] = idx/32).
//             On mismatch, atomicOr a __device__ flag. The flag is
//             zero-initialized at module load and is ONLY ever set when the
//             lut differs from identity; since the lut buffer is identical on
//             every call, the flag value is a pure function of the inputs —
//             deterministic across graph replays with no reset kernel needed.
//   kernel 2: flag==0 -> out = x * (1/1.000001)   (trilinear interp of a
//             linear ramp is exactly linear)       -- pure HBM stream
//             flag!=0 -> full trilinear gather from the raw lut (correct but
//             slower; never taken for this problem's inputs)

#define DIM   33
#define DIM2  (DIM * DIM)       // 1089
#define DIM3  (DIM * DIM * DIM) // 35937

__device__ int g_not_identity;   // zero-initialized; see header comment

__global__ void check_lut_kernel(const float* __restrict__ lut) {
    int i = blockIdx.x * blockDim.x + threadIdx.x;
    if (i >= DIM3) return;
    float r = __ldg(&lut[i]);
    float g = __ldg(&lut[DIM3 + i]);
    float b = __ldg(&lut[2 * DIM3 + i]);

    int ri = i % DIM;
    int gi = (i / DIM) % DIM;
    int bi = i / DIM2;
    const float s = 1.0f / 32.0f;
    if (fabsf(r - (float)ri * s) > 2e-6f ||
        fabsf(g - (float)gi * s) > 2e-6f ||
        fabsf(b - (float)bi * s) > 2e-6f) {
        atomicOr(&g_not_identity, 1);
    }
}

// ---- slow path (generic lut), scalar gathers from raw lut ----
__device__ __forceinline__ float trilerp_ch(const float* __restrict__ lc,
                                            int base, float rd, float gd, float bd) {
    float c000 = __ldg(&lc[base]);
    float c001 = __ldg(&lc[base + 1]);
    float c010 = __ldg(&lc[base + DIM]);
    float c011 = __ldg(&lc[base + DIM + 1]);
    float c100 = __ldg(&lc[base + DIM2]);
    float c101 = __ldg(&lc[base + DIM2 + 1]);
    float c110 = __ldg(&lc[base + DIM2 + DIM]);
    float c111 = __ldg(&lc[base + DIM2 + DIM + 1]);
    float c00 = fmaf(rd, c001 - c000, c000);
    float c01 = fmaf(rd, c011 - c010, c010);
    float c10 = fmaf(rd, c101 - c100, c100);
    float c11 = fmaf(rd, c111 - c110, c110);
    float c0  = fmaf(gd, c01 - c00, c00);
    float c1  = fmaf(gd, c11 - c10, c10);
    return fmaf(bd, c1 - c0, c0);
}

__device__ __forceinline__ void trilinear_one(const float* __restrict__ lut,
                                              float r, float g, float b,
                                              float& orr, float& ogg, float& obb) {
    const float invbin = 32.0f / 1.000001f;   // 1/binsize
    float rs = r * invbin, gs = g * invbin, bs = b * invbin;
    float rf = floorf(rs), gf = floorf(gs), bf = floorf(bs);
    float rd = rs - rf, gd = gs - gf, bd = bs - bf;
    int ri = min(max((int)rf, 0), DIM - 2);
    int gi = min(max((int)gf, 0), DIM - 2);
    int bi = min(max((int)bf, 0), DIM - 2);
    int base = (bi * DIM + gi) * DIM + ri;
    orr = trilerp_ch(lut,            base, rd, gd, bd);
    ogg = trilerp_ch(lut + DIM3,     base, rd, gd, bd);
    obb = trilerp_ch(lut + 2 * DIM3, base, rd, gd, bd);
}

// x layout per image: [3][1024*1024] planes; 8 images.
// Each thread handles 4 consecutive pixels (one float4 per channel plane).
#define PIX_PER_IMG   (1024 * 1024)          // 2^20
#define VEC_PER_IMG   (PIX_PER_IMG / 4)      // 2^18
#define TOTAL_VEC     (8 * VEC_PER_IMG)      // 2^21
#define THREADS       256

__global__ __launch_bounds__(THREADS)
void apply_lut_kernel(const float* __restrict__ x,
                      const float* __restrict__ lut,
                      float* __restrict__ out) {
    int idx = blockIdx.x * THREADS + threadIdx.x;   // < 2^21, exact grid
    int img = idx >> 18;
    int off = (idx & (VEC_PER_IMG - 1)) << 2;       // float offset within plane

    long long ibase = (long long)img * (3LL * PIX_PER_IMG) + off;
    const float4* xr = (const float4*)(x + ibase);
    const float4* xg = (const float4*)(x + ibase + PIX_PER_IMG);
    const float4* xb = (const float4*)(x + ibase + 2 * PIX_PER_IMG);

    float4 orr, ogg, obb;

    if (g_not_identity == 0) {
        // Identity LUT: trilinear interp of linear ramp == x / 1.000001.
        // Streaming loads/stores: 192 MB footprint > L2, no reuse.
        const float s = 1.0f / 1.000001f;
        float4 r4 = __ldcs(xr), g4 = __ldcs(xg), b4 = __ldcs(xb);
        orr.x = r4.x * s; orr.y = r4.y * s; orr.z = r4.z * s; orr.w = r4.w * s;
        ogg.x = g4.x * s; ogg.y = g4.y * s; ogg.z = g4.z * s; ogg.w = g4.w * s;
        obb.x = b4.x * s; obb.y = b4.y * s; obb.z = b4.z * s; obb.w = b4.w * s;
        __stcs((float4*)(out + ibase),                   orr);
        __stcs((float4*)(out + ibase + PIX_PER_IMG),     ogg);
        __stcs((float4*)(out + ibase + 2 * PIX_PER_IMG), obb);
    } else {
        float4 r4 = *xr, g4 = *xg, b4 = *xb;
        trilinear_one(lut, r4.x, g4.x, b4.x, orr.x, ogg.x, obb.x);
        trilinear_one(lut, r4.y, g4.y, b4.y, orr.y, ogg.y, obb.y);
        trilinear_one(lut, r4.z, g4.z, b4.z, orr.z, ogg.z, obb.z);
        trilinear_one(lut, r4.w, g4.w, b4.w, orr.w, ogg.w, obb.w);
        *(float4*)(out + ibase)                    = orr;
        *(float4*)(out + ibase + PIX_PER_IMG)      = ogg;
        *(float4*)(out + ibase + 2 * PIX_PER_IMG)  = obb;
    }
}

extern "C" void kernel_launch(void* const* d_in, const int* in_sizes, int n_in,
                              void* d_out, int out_size) {
    const float* lut = (const float*)d_in[0];
    const float* x   = (const float*)d_in[1];
    // defensive: identify lut by element count (3*33^3 = 107811)
    if (n_in >= 2 && in_sizes[0] != 3 * DIM3 && in_sizes[1] == 3 * DIM3) {
        lut = (const float*)d_in[1];
        x   = (const float*)d_in[0];
    }
    float* out = (float*)d_out;

    check_lut_kernel<<<(DIM3 + 255) / 256, 256>>>(lut);
    apply_lut_kernel<<<TOTAL_VEC / THREADS, THREADS>>>(x, lut, out);
}